// round 6
// baseline (speedup 1.0000x reference)
#include <cuda_runtime.h>

#define T_STEPS 8192
#define UNITS   2048
#define INDIM   512
#define RNN_BLOCKS 128
#define ROWS_PB 16   // UNITS / RNN_BLOCKS

__device__ unsigned long long g_bar;
__device__ float g_xin[(size_t)T_STEPS * UNITS];   // 64 MB scratch (static, allowed)

__global__ void reset_bar() { g_bar = 0ULL; }

// ---------------------------------------------------------------------------
// Kernel 1: xin[t][u] = dot(x[t], wax[u]) + ba[u]
// 128x128 register-tiled SGEMM (A=x [T,K], B=wax [U,K], both K-major),
// accumulating with packed fp32 FFMA2 (fma.rn.f32x2).
// grid = (UNITS/128, T/128), block = 256 threads, 8x8 microtile per thread.
// ---------------------------------------------------------------------------
__global__ void __launch_bounds__(256) xin_gemm(const float* __restrict__ x,
                                                const float* __restrict__ wax,
                                                const float* __restrict__ ba) {
    __shared__ float As[8][128];
    __shared__ float Bs[8][128];
    const int tid = threadIdx.x;
    const int t0 = blockIdx.y * 128;
    const int u0 = blockIdx.x * 128;
    const int lr = tid >> 1;            // 0..127 row within tile
    const int lk = (tid & 1) * 4;       // 0 or 4: k-quad
    const float* xg = x   + (size_t)(t0 + lr) * INDIM + lk;
    const float* wg = wax + (size_t)(u0 + lr) * INDIM + lk;
    const int ty = tid >> 4, tx = tid & 15;
    const int m = ty * 8, n = tx * 8;

    unsigned long long cc[8][4];
#pragma unroll
    for (int i = 0; i < 8; i++)
#pragma unroll
        for (int j = 0; j < 4; j++) cc[i][j] = 0ULL;

    for (int k0 = 0; k0 < INDIM; k0 += 8) {
        float4 av = *(const float4*)(xg + k0);
        float4 bv = *(const float4*)(wg + k0);
        As[lk + 0][lr] = av.x; As[lk + 1][lr] = av.y;
        As[lk + 2][lr] = av.z; As[lk + 3][lr] = av.w;
        Bs[lk + 0][lr] = bv.x; Bs[lk + 1][lr] = bv.y;
        Bs[lk + 2][lr] = bv.z; Bs[lk + 3][lr] = bv.w;
        __syncthreads();
#pragma unroll
        for (int k = 0; k < 8; k++) {
            float4 a0 = *(const float4*)&As[k][m];
            float4 a1 = *(const float4*)&As[k][m + 4];
            ulonglong2 b0 = *(const ulonglong2*)&Bs[k][n];
            ulonglong2 b1 = *(const ulonglong2*)&Bs[k][n + 4];
            float aa[8] = {a0.x, a0.y, a0.z, a0.w, a1.x, a1.y, a1.z, a1.w};
            unsigned long long bb[4] = {b0.x, b0.y, b1.x, b1.y};
#pragma unroll
            for (int i = 0; i < 8; i++) {
                unsigned ai = __float_as_uint(aa[i]);
                unsigned long long ad;
                asm("mov.b64 %0, {%1, %1};" : "=l"(ad) : "r"(ai));
#pragma unroll
                for (int j = 0; j < 4; j++)
                    asm("fma.rn.f32x2 %0, %1, %2, %0;"
                        : "+l"(cc[i][j]) : "l"(ad), "l"(bb[j]));
            }
        }
        __syncthreads();
    }
#pragma unroll
    for (int i = 0; i < 8; i++) {
#pragma unroll
        for (int j = 0; j < 4; j++) {
            int uu = u0 + n + j * 2;
            float lo = __uint_as_float((unsigned)(cc[i][j])) + ba[uu];
            float hi = __uint_as_float((unsigned)(cc[i][j] >> 32)) + ba[uu + 1];
            *(float2*)&g_xin[(size_t)(t0 + m + i) * UNITS + uu] = make_float2(lo, hi);
        }
    }
}

// ---------------------------------------------------------------------------
// Kernel 2: persistent RNN scan. 128 CTAs x 1024 threads, waa in registers.
// Thread (warp w, lane l): row = blk*16 + (l&15), cols [w*64 + (l>>4)*32, +32).
// Per step: a -> smem, FFMA2 partials, shfl+smem reduce, tanh, STG to out[t],
// release/acquire grid barrier on g_bar.
// ---------------------------------------------------------------------------
__global__ void __launch_bounds__(1024, 1) rnn_kernel(const float* __restrict__ waa,
                                                      float* __restrict__ out) {
    __shared__ float sa[UNITS];            // current a vector
    __shared__ float red[32][17];          // cross-warp partials (padded)
    __shared__ float xin_s[2][ROWS_PB];    // double-buffered xin prefetch

    const int tid = threadIdx.x;
    const int w = tid >> 5;
    const int l = tid & 31;
    const int r = l & 15;                  // local row 0..15
    const int h = l >> 4;                  // column half 0/1
    const int cb = w * 64 + h * 32;        // this thread's column base
    const int r0 = blockIdx.x * ROWS_PB;
    const int row = r0 + r;

    // Load this thread's 32 waa coefficients into registers as 16 f32x2 pairs.
    unsigned long long wreg[16];
    {
        const unsigned long long* wp =
            (const unsigned long long*)(waa + (size_t)row * UNITS + cb);
#pragma unroll
        for (int i = 0; i < 16; i++) wreg[i] = wp[i];
    }

    const unsigned long long* sa64 = (const unsigned long long*)sa;
    unsigned long long* barp = &g_bar;

    // Prefetch xin[0] for this block's rows.
    if (tid < ROWS_PB) xin_s[0][tid] = g_xin[r0 + tid];

    for (int t = 0; t < T_STEPS; t++) {
        // --- stage a_{t-1} into shared (zeros at t=0) ---
        if (t == 0) {
            ((float2*)sa)[tid] = make_float2(0.f, 0.f);
        } else {
            ((float2*)sa)[tid] = ((const float2*)(out + (size_t)(t - 1) * UNITS))[tid];
        }
        // prefetch next step's xin (consumed in next iteration's phase 2)
        if (tid < ROWS_PB && t + 1 < T_STEPS)
            xin_s[(t + 1) & 1][tid] = g_xin[(size_t)(t + 1) * UNITS + r0 + tid];
        __syncthreads();

        // --- partial dot product: 32 MACs as 16 FFMA2 ---
        unsigned long long acc = 0ULL;   // packed (0.f, 0.f)
        const int base = cb >> 1;
#pragma unroll
        for (int i = 0; i < 16; i++) {
            unsigned long long av = sa64[base + i];
            asm("fma.rn.f32x2 %0, %1, %2, %0;" : "+l"(acc) : "l"(wreg[i]), "l"(av));
        }
        float s = __uint_as_float((unsigned)acc) +
                  __uint_as_float((unsigned)(acc >> 32));
        // combine the two column halves (lanes r and r+16 share a row)
        s += __shfl_xor_sync(0xffffffffu, s, 16);
        if (l < 16) red[w][l] = s;
        __syncthreads();

        // --- phase 2: warp r reduces 32 warp-partials for row r ---
        if (w < 16) {
            float v = red[l][w];
            v += __shfl_xor_sync(0xffffffffu, v, 16);   // full 32-lane butterfly
            v += __shfl_xor_sync(0xffffffffu, v, 8);
            v += __shfl_xor_sync(0xffffffffu, v, 4);
            v += __shfl_xor_sync(0xffffffffu, v, 2);
            v += __shfl_xor_sync(0xffffffffu, v, 1);
            if (l == 0) {
                float y = tanhf(v + xin_s[t & 1][w]);
                out[(size_t)t * UNITS + r0 + w] = y;
            }
        }
        __syncthreads();

        // --- grid barrier (skip after last step) ---
        if (t + 1 < T_STEPS) {
            if (tid == 0) {
                unsigned long long target =
                    (unsigned long long)(t + 1) * (unsigned long long)RNN_BLOCKS;
                unsigned long long oldv;
                asm volatile("atom.release.gpu.add.u64 %0, [%1], %2;"
                             : "=l"(oldv) : "l"(barp), "l"(1ULL) : "memory");
                unsigned long long v;
                do {
                    asm volatile("ld.acquire.gpu.b64 %0, [%1];"
                                 : "=l"(v) : "l"(barp) : "memory");
                } while (v < target);
            }
            __syncthreads();
        }
    }
}

extern "C" void kernel_launch(void* const* d_in, const int* in_sizes, int n_in,
                              void* d_out, int out_size) {
    const float* x   = (const float*)d_in[0];   // [1, 8192, 512]
    const float* waa = (const float*)d_in[1];   // [2048, 2048]
    const float* wax = (const float*)d_in[2];   // [2048, 512]
    const float* ba  = (const float*)d_in[3];   // [2048, 1]
    float* out = (float*)d_out;                  // [1, 8192, 2048]

    reset_bar<<<1, 1>>>();
    dim3 gg(UNITS / 128, T_STEPS / 128);
    xin_gemm<<<gg, 256>>>(x, wax, ba);
    rnn_kernel<<<RNN_BLOCKS, 1024>>>(waa, out);
}